// round 17
// baseline (speedup 1.0000x reference)
#include <cuda_runtime.h>
#include <cstddef>

// LSTM_31018253812286 — v12: v11b with the head UNFUSED.
// Post-mortem v11b (6792us, fma=57%, issue=47%, regs=128-pinned): the 48-reg
// fused-head accumulator clamps the kernel at the register cap (spills) and
// the h LDS is consumed with no prefetch distance. DRAM is idle (0.1%) ->
// stream h to __device__ scratch (32B-sector STG) and run a tiny memory-bound
// head kernel; mainloop drops to ~92 regs and gains a d1 h prefetch.
//
// B=131072, T=5, I=13, H=256, OUT=6.
// Main CTA: TB=64, 512 threads, 16 warps = 8 batch-octets x 2 n-halves.
// Warp (oct,nh): batches b0=8*oct..+8; n = nh*128 + ch*32 + lane, 4 chunks.
// acc = f32x2 batch pairs (fma.rn.f32x2). Weights [k][n][4g]: one LDG.128/k
// covers all 4 gates (64 weight wf/SM per 128-cyc FMA window), d2 prefetch.
// h/c in smem stride 68; oct-pair named barrier orders the two nh warps.

#define H_   256
#define IN_  13
#define T_   5
#define OUT_ 6
#define TB   64
#define HS   68
#define NTHREADS 512
#define BMAX 131072

typedef unsigned long long u64;

__device__ __forceinline__ u64 pack2(float x) {
    u64 r; asm("mov.b64 %0, {%1, %1};" : "=l"(r) : "f"(x)); return r;
}
__device__ __forceinline__ void fma2(u64& d, u64 a, u64 b) {
    asm("fma.rn.f32x2 %0, %1, %2, %0;" : "+l"(d) : "l"(a), "l"(b));
}
__device__ __forceinline__ float2 unpack2(u64 v) {
    float2 r; asm("mov.b64 {%0, %1}, %2;" : "=f"(r.x), "=f"(r.y) : "l"(v)); return r;
}

// __device__ scratch (no allocations). 16B-aligned where vector-loaded.
__device__ __align__(16) float g_W3[H_ * H_ * 4];     // [k][n][4g]
__device__ __align__(16) float g_Wi3[IN_ * H_ * 4];   // [i][n][4g]
__device__ __align__(16) float g_b3[H_ * 4];          // [n][4g]
__device__ __align__(16) float g_W1p[T_ * H_ * 8];    // [tn][8] (o<6 used)
__device__ __align__(16) float g_hall[T_ * H_ * BMAX]; // h stream [t][n][b]

__global__ void lstm_prep_31018253812286(const float* __restrict__ W_ih,
                                         const float* __restrict__ W_hh,
                                         const float* __restrict__ b_ih,
                                         const float* __restrict__ b_hh,
                                         const float* __restrict__ W1) {
    const int stride = gridDim.x * blockDim.x;
    const int idx0 = blockIdx.x * blockDim.x + threadIdx.x;
    for (int idx = idx0; idx < 4 * H_ * H_; idx += stride) {
        int row = idx / H_;
        int k   = idx - row * H_;
        int g   = row >> 8;
        int n   = row & (H_ - 1);
        g_W3[(k * H_ + n) * 4 + g] = W_hh[idx];
    }
    for (int idx = idx0; idx < 4 * H_ * IN_; idx += stride) {
        int row = idx / IN_;
        int i   = idx - row * IN_;
        int g   = row >> 8;
        int n   = row & (H_ - 1);
        g_Wi3[(i * H_ + n) * 4 + g] = W_ih[idx];
    }
    for (int idx = idx0; idx < 4 * H_; idx += stride) {
        int g = idx >> 8;
        int n = idx & (H_ - 1);
        g_b3[n * 4 + g] = b_ih[idx] + b_hh[idx];
    }
    for (int idx = idx0; idx < OUT_ * T_ * H_; idx += stride) {
        int o = idx / (T_ * H_);
        int r = idx - o * (T_ * H_);
        g_W1p[r * 8 + o] = W1[idx];
    }
}

__device__ __forceinline__ float sigmoid_f(float x) {
    return __fdividef(1.0f, 1.0f + __expf(-x));
}
__device__ __forceinline__ float tanh_f(float x) {
    return __fdividef(2.0f, 1.0f + __expf(-2.0f * x)) - 1.0f;
}

__global__ void __launch_bounds__(NTHREADS, 1)
lstm_main_31018253812286(const float* __restrict__ x, int B) {
    extern __shared__ float smem[];
    float* h_s = smem;                       // [2][H_][HS]
    float* c_s = smem + 2 * H_ * HS;         // [H_][HS]
    float* x_s = smem + 3 * H_ * HS;         // [T_][IN_][TB]

    const int tid = threadIdx.x;
    const int tn  = tid & 31;        // lane -> n within chunk
    const int w   = tid >> 5;
    const int oct = w & 7;           // batch octet
    const int nh  = w >> 3;          // n-half
    const int b0  = oct * 8;
    const int gb0 = blockIdx.x * TB + b0;   // global batch base

    // Stage x (coalesced read, transposed store) + zero c_s.
    {
        const float* xg = x + (size_t)blockIdx.x * TB * (T_ * IN_);
        for (int idx = tid; idx < TB * T_ * IN_; idx += NTHREADS) {
            int b = idx / (T_ * IN_);
            int r = idx - b * (T_ * IN_);
            int t = r / IN_;
            int i = r - t * IN_;
            x_s[(t * IN_ + i) * TB + b] = xg[idx];
        }
        for (int idx = tid; idx < H_ * HS; idx += NTHREADS)
            c_s[idx] = 0.0f;
    }
    __syncthreads();

    for (int t = 0; t < T_; t++) {
        const int wbuf = t & 1;
        const float* hread  = h_s + (wbuf ^ 1) * (H_ * HS);
        float*       hwrite = h_s + wbuf * (H_ * HS);

        #pragma unroll
        for (int ch = 0; ch < 4; ch++) {
            const int n = nh * 128 + ch * 32 + tn;
            u64 acc[4][4];           // [gate][batch-pair]

            // Bias splat per gate (n-uniform across batch lanes).
            {
                float4 bv = *(const float4*)(g_b3 + n * 4);
                u64 bs[4] = {pack2(bv.x), pack2(bv.y), pack2(bv.z), pack2(bv.w)};
                #pragma unroll
                for (int g = 0; g < 4; g++)
                    #pragma unroll
                    for (int bp = 0; bp < 4; bp++) acc[g][bp] = bs[g];
            }

            // Input projection (13 k-steps).
            #pragma unroll
            for (int i = 0; i < IN_; i++) {
                float4 wv4 = *(const float4*)(g_Wi3 + (i * H_ + n) * 4);
                u64 ws[4] = {pack2(wv4.x), pack2(wv4.y), pack2(wv4.z), pack2(wv4.w)};
                const float* xrow = x_s + (t * IN_ + i) * TB + b0;
                ulonglong2 xp0 = *(const ulonglong2*)(xrow);
                ulonglong2 xp1 = *(const ulonglong2*)(xrow + 4);
                u64 xp[4] = {xp0.x, xp0.y, xp1.x, xp1.y};
                #pragma unroll
                for (int g = 0; g < 4; g++)
                    #pragma unroll
                    for (int bp = 0; bp < 4; bp++) fma2(acc[g][bp], ws[g], xp[bp]);
            }

            // Recurrent GEMM (skipped at t=0). Weight prefetch d2 (L2 ~250cyc
            // covered by ~512cyc) + h prefetch d1 (LDS 29cyc covered).
            if (t > 0) {
                float4 wA = *(const float4*)(g_W3 + (0 * H_ + n) * 4);
                float4 wB = *(const float4*)(g_W3 + (1 * H_ + n) * 4);
                ulonglong2 hA0 = *(const ulonglong2*)(hread + b0);
                ulonglong2 hA1 = *(const ulonglong2*)(hread + b0 + 4);
                #pragma unroll 4
                for (int kk = 0; kk < H_; kk++) {
                    float4 wv4 = wA; wA = wB;
                    if (kk + 2 < H_)
                        wB = *(const float4*)(g_W3 + ((kk + 2) * H_ + n) * 4);
                    u64 hp[4] = {hA0.x, hA0.y, hA1.x, hA1.y};
                    if (kk + 1 < H_) {
                        const float* hrow = hread + (kk + 1) * HS + b0;
                        hA0 = *(const ulonglong2*)(hrow);
                        hA1 = *(const ulonglong2*)(hrow + 4);
                    }
                    u64 ws[4] = {pack2(wv4.x), pack2(wv4.y), pack2(wv4.z), pack2(wv4.w)};
                    #pragma unroll
                    for (int g = 0; g < 4; g++)
                        #pragma unroll
                        for (int bp = 0; bp < 4; bp++) fma2(acc[g][bp], ws[g], hp[bp]);
                }
            }

            // Epilogue: activations, c/h smem update, h stream to global.
            {
                float* crow = c_s + n * HS + b0;
                float4 c0 = *(const float4*)(crow);
                float4 c1 = *(const float4*)(crow + 4);
                float cold[8] = {c0.x, c0.y, c0.z, c0.w, c1.x, c1.y, c1.z, c1.w};

                float hq[8], cnew[8];
                #pragma unroll
                for (int bp = 0; bp < 4; bp++) {
                    float2 iv2 = unpack2(acc[0][bp]);
                    float2 fv2 = unpack2(acc[1][bp]);
                    float2 gv2 = unpack2(acc[2][bp]);
                    float2 ov2 = unpack2(acc[3][bp]);
                    #pragma unroll
                    for (int hf = 0; hf < 2; hf++) {
                        int b = bp * 2 + hf;
                        float iv = sigmoid_f(hf ? iv2.y : iv2.x);
                        float fv = sigmoid_f(hf ? fv2.y : fv2.x);
                        float gv = tanh_f(hf ? gv2.y : gv2.x);
                        float ov = sigmoid_f(hf ? ov2.y : ov2.x);
                        float cv = fmaf(fv, cold[b], iv * gv);
                        cnew[b] = cv;
                        hq[b] = ov * tanh_f(cv);
                    }
                }

                *(float4*)(crow)     = make_float4(cnew[0], cnew[1], cnew[2], cnew[3]);
                *(float4*)(crow + 4) = make_float4(cnew[4], cnew[5], cnew[6], cnew[7]);
                float* hrow = hwrite + n * HS + b0;
                *(float4*)(hrow)     = make_float4(hq[0], hq[1], hq[2], hq[3]);
                *(float4*)(hrow + 4) = make_float4(hq[4], hq[5], hq[6], hq[7]);

                // Stream h to global scratch (32B sector-aligned, fire & forget).
                float* gall = g_hall + (size_t)(t * H_ + n) * B + gb0;
                *(float4*)(gall)     = make_float4(hq[0], hq[1], hq[2], hq[3]);
                *(float4*)(gall + 4) = make_float4(hq[4], hq[5], hq[6], hq[7]);
            }
        }
        // h is shared between the two nh-warps of this octet: named barrier
        // over the 64-thread pair (ids 1..8; id 0 is __syncthreads).
        asm volatile("bar.sync %0, 64;" :: "r"(oct + 1) : "memory");
    }
}

// Head: out[b][o] = b1[o] + sum_tn hall[tn][b] * W1[o][tn]. Memory-bound
// (671MB coalesced read); W1 via prefolded [tn][8] rows (L1-hot uniform).
__global__ void __launch_bounds__(256)
lstm_head_31018253812286(const float* __restrict__ b1,
                         float* __restrict__ out, int B) {
    const int b = blockIdx.x * 256 + threadIdx.x;
    if (b >= B) return;
    float acc[OUT_];
    #pragma unroll
    for (int o = 0; o < OUT_; o++) acc[o] = b1[o];
    #pragma unroll 4
    for (int tn = 0; tn < T_ * H_; tn++) {
        float hv = g_hall[(size_t)tn * B + b];        // coalesced
        const float* wr = g_W1p + tn * 8;             // uniform, L1-hot
        float4 wa = *(const float4*)(wr);
        float2 wb2 = *(const float2*)(wr + 4);
        acc[0] = fmaf(hv, wa.x, acc[0]);
        acc[1] = fmaf(hv, wa.y, acc[1]);
        acc[2] = fmaf(hv, wa.z, acc[2]);
        acc[3] = fmaf(hv, wa.w, acc[3]);
        acc[4] = fmaf(hv, wb2.x, acc[4]);
        acc[5] = fmaf(hv, wb2.y, acc[5]);
    }
    #pragma unroll
    for (int o = 0; o < OUT_; o++) out[b * OUT_ + o] = acc[o];
}

extern "C" void kernel_launch(void* const* d_in, const int* in_sizes, int n_in,
                              void* d_out, int out_size) {
    const float* x    = (const float*)d_in[0];  // [B,5,13]
    const float* W_ih = (const float*)d_in[1];  // [1024,13]
    const float* W_hh = (const float*)d_in[2];  // [1024,256]
    const float* b_ih = (const float*)d_in[3];  // [1024]
    const float* b_hh = (const float*)d_in[4];  // [1024]
    const float* W1   = (const float*)d_in[5];  // [6,1280]
    const float* b1   = (const float*)d_in[6];  // [6]
    float* out = (float*)d_out;                 // [B,6]

    const int B = in_sizes[0] / (T_ * IN_);     // 131072
    const int smem_bytes = (3 * H_ * HS + T_ * IN_ * TB) * (int)sizeof(float); // 225536

    cudaFuncSetAttribute(lstm_main_31018253812286,
                         cudaFuncAttributeMaxDynamicSharedMemorySize, smem_bytes);

    lstm_prep_31018253812286<<<64, 256>>>(W_ih, W_hh, b_ih, b_hh, W1);
    lstm_main_31018253812286<<<B / TB, NTHREADS, smem_bytes>>>(x, B);
    lstm_head_31018253812286<<<(B + 255) / 256, 256>>>(b1, out, B);
}